// round 7
// baseline (speedup 1.0000x reference)
#include <cuda_runtime.h>
#include <cuda_bf16.h>
#include <cstdint>
#include <math.h>

// Problem constants
#define B_SZ   4
#define S_SZ   8192
#define D_SZ   512
#define H_SZ   8
#define HD_SZ  64
#define N_TOK  (B_SZ * S_SZ)          // 32768
#define BH_SZ  (B_SZ * H_SZ)          // 32

// ---------------- scratch (static __device__, no allocations) ----------------
__device__ __nv_bfloat16 g_xh[(size_t)N_TOK * D_SZ];
__device__ __nv_bfloat16 g_xl[(size_t)N_TOK * D_SZ];
__device__ __nv_bfloat16 g_wth[4 * D_SZ * D_SZ];   // transposed weights, hi
__device__ __nv_bfloat16 g_wtl[4 * D_SZ * D_SZ];   // transposed weights, lo
__device__ float g_q[(size_t)N_TOK * D_SZ];
__device__ float g_k[(size_t)N_TOK * D_SZ];
__device__ float g_v[(size_t)N_TOK * D_SZ];
__device__ __nv_bfloat16 g_ah[(size_t)N_TOK * D_SZ];
__device__ __nv_bfloat16 g_al[(size_t)N_TOK * D_SZ];
__device__ float g_y[(size_t)N_TOK * D_SZ];
__device__ float g_kv[BH_SZ * HD_SZ * HD_SZ];
__device__ float g_ksum[BH_SZ * HD_SZ];

// ======================= helpers ==============================================
__device__ __forceinline__ uint32_t smem_u32(const void* p) {
    uint32_t a;
    asm("{ .reg .u64 t; cvta.to.shared.u64 t, %1; cvt.u32.u64 %0, t; }"
        : "=r"(a) : "l"(p));
    return a;
}
__device__ __forceinline__ void cpa16(uint32_t dst, const void* src) {
    asm volatile("cp.async.cg.shared.global [%0], [%1], 16;" :: "r"(dst), "l"(src));
}
#define CPA_COMMIT() asm volatile("cp.async.commit_group;" ::: "memory")
#define CPA_WAIT(n)  asm volatile("cp.async.wait_group %0;" :: "n"(n) : "memory")

#define LDSM4(r, addr)                                                          \
    asm volatile("ldmatrix.sync.aligned.m8n8.x4.shared.b16 {%0,%1,%2,%3}, [%4];"\
                 : "=r"((r)[0]), "=r"((r)[1]), "=r"((r)[2]), "=r"((r)[3])       \
                 : "r"(addr))

// HMMA: D(16x8,f32) += A(16x16,bf16,row) * B(16x8,bf16,col)
__device__ __forceinline__ void mma16816(float* d, const uint32_t* a, const uint32_t* b) {
    asm volatile(
        "mma.sync.aligned.m16n8k16.row.col.f32.bf16.bf16.f32 "
        "{%0,%1,%2,%3}, {%4,%5,%6,%7}, {%8,%9}, {%0,%1,%2,%3};"
        : "+f"(d[0]), "+f"(d[1]), "+f"(d[2]), "+f"(d[3])
        : "r"(a[0]), "r"(a[1]), "r"(a[2]), "r"(a[3]), "r"(b[0]), "r"(b[1]));
}

__device__ __forceinline__ void split2(float v, __nv_bfloat16& h, __nv_bfloat16& l) {
    h = __float2bfloat16(v);
    l = __float2bfloat16(v - __bfloat162float(h));
}

// ======================= conversion kernels ===================================
__global__ __launch_bounds__(256) void convert_x_kernel(const float* __restrict__ x)
{
    size_t i = (size_t)blockIdx.x * 256 + threadIdx.x;   // float4 index
    float4 v = ((const float4*)x)[i];
    __nv_bfloat16 h[4], l[4];
    split2(v.x, h[0], l[0]); split2(v.y, h[1], l[1]);
    split2(v.z, h[2], l[2]); split2(v.w, h[3], l[3]);
    *(uint2*)&g_xh[4 * i] = *(uint2*)h;
    *(uint2*)&g_xl[4 * i] = *(uint2*)l;
}

// transpose + split 4 weights: Wt[w][n][k] = W_w[k][n]
__global__ void convert_w_kernel(const float* __restrict__ Wq, const float* __restrict__ Wk,
                                 const float* __restrict__ Wv, const float* __restrict__ Wo)
{
    __shared__ float tile[32][33];
    const int w = blockIdx.z;
    const float* W = (w == 0) ? Wq : (w == 1) ? Wk : (w == 2) ? Wv : Wo;
    int tx = threadIdx.x, ty = threadIdx.y;
    int k = blockIdx.y * 32 + ty;
    int n = blockIdx.x * 32 + tx;
    tile[ty][tx] = W[k * D_SZ + n];
    __syncthreads();
    int nn = blockIdx.x * 32 + ty;
    int kk = blockIdx.y * 32 + tx;
    float v = tile[tx][ty];
    __nv_bfloat16 h, l;
    split2(v, h, l);
    size_t idx = (size_t)w * D_SZ * D_SZ + (size_t)nn * D_SZ + kk;
    g_wth[idx] = h;
    g_wtl[idx] = l;
}

// ======================= tensor-core GEMM (mma.sync bf16, split) ==============
// CTA tile 128x128, BK=32, 256 threads (8 warps, 4x2), warp tile 32x64.
// 2-stage cp.async pipeline; 4-phase inner loop with B-fragment prefetch.
// MODE 0: fused QKV (N_total=1536, featmap for q/k, select by n0>>9)
// MODE 2: Wo (+bias, +resid)
#define BKC     32
#define RSTRIDE 80           // bytes per smem row (32 bf16 + 16 pad)
#define A_BYTES (128 * RSTRIDE)
#define B_BYTES (128 * RSTRIDE)
#define AH_OFF  0
#define AL_OFF  (A_BYTES)
#define BH_OFF  (2 * A_BYTES)
#define BL_OFF  (2 * A_BYTES + B_BYTES)
#define STAGE_BYTES (2 * A_BYTES + 2 * B_BYTES)   // 40960
#define NSTAGE  2
#define NCHUNK  (D_SZ / BKC)                      // 16

template <int MODE>
__global__ __launch_bounds__(256, 2)
void gemm_tc(const __nv_bfloat16* __restrict__ Ah, const __nv_bfloat16* __restrict__ Al,
             const __nv_bfloat16* __restrict__ Bh, const __nv_bfloat16* __restrict__ Bl,
             const float* __restrict__ b0p, const float* __restrict__ b1p,
             const float* __restrict__ b2p, const float* __restrict__ resid,
             float* __restrict__ C0, float* __restrict__ C1, float* __restrict__ C2)
{
    extern __shared__ __align__(16) char dsm[];
    const uint32_t sb = smem_u32(dsm);

    const int t    = threadIdx.x;
    const int lane = t & 31;
    const int wid  = t >> 5;
    const int wm   = wid >> 1;          // 0..3  (32-row group)
    const int wn   = wid & 1;           // 0..1  (64-col group)
    const int m0   = blockIdx.y * 128;
    const int n0   = blockIdx.x * 128;

    float acc[2][8][4];
#pragma unroll
    for (int i = 0; i < 2; i++)
#pragma unroll
        for (int j = 0; j < 8; j++)
#pragma unroll
            for (int r = 0; r < 4; r++) acc[i][j][r] = 0.f;

    // per-lane ldmatrix address components
    const uint32_t aoff = (uint32_t)(wm * 32 + (lane & 15)) * RSTRIDE
                        + ((lane >> 4) & 1) * 16;
    const uint32_t boff = (uint32_t)(wn * 64 + (lane & 7) + ((lane >> 4) & 1) * 8) * RSTRIDE
                        + ((lane >> 3) & 1) * 16;

    // ---- async tile loader (BK=32: 64B per row, 4 x 16B parts) ----
    auto load_chunk = [&](int kc, int stage) {
        const uint32_t base = sb + stage * STAGE_BYTES;
        const size_t gkoff = (size_t)kc * BKC;
#pragma unroll
        for (int e = 0; e < 2; e++) {            // A: 128 rows x 4 parts = 512
            int id   = t + e * 256;
            int row  = id >> 2;
            int part = id & 3;
            uint32_t doff = row * RSTRIDE + part * 16;
            size_t   goff = (size_t)(m0 + row) * D_SZ + gkoff + part * 8;
            cpa16(base + AH_OFF + doff, Ah + goff);
            cpa16(base + AL_OFF + doff, Al + goff);
        }
#pragma unroll
        for (int e = 0; e < 2; e++) {            // B: 128 rows x 4 parts = 512
            int id   = t + e * 256;
            int row  = id >> 2;
            int part = id & 3;
            uint32_t doff = row * RSTRIDE + part * 16;
            size_t   goff = (size_t)(n0 + row) * D_SZ + gkoff + part * 8;
            cpa16(base + BH_OFF + doff, Bh + goff);
            cpa16(base + BL_OFF + doff, Bl + goff);
        }
        CPA_COMMIT();
    };

    // ---- compute one BK=32 chunk: 4 phases (kk,nh), B-frags double-buffered --
    auto compute_chunk = [&](int stage) {
        const uint32_t base = sb + stage * STAGE_BYTES;
        const uint32_t aH = base + AH_OFF + aoff;
        const uint32_t aL = base + AL_OFF + aoff;
        const uint32_t bH = base + BH_OFF + boff;
        const uint32_t bL = base + BL_OFF + boff;

        uint32_t fah[2][4], fal[2][4];           // A frags, current kk
        uint32_t fbh[2][2][4], fbl[2][2][4];     // B frags, double-buffered

        // phase p: kk = p>>1, nh = p&1, buffer = p&1
        // B offsets: kk*32 bytes + nh*32*RSTRIDE
        LDSM4(fah[0], aH);
        LDSM4(fah[1], aH + 16 * RSTRIDE);
        LDSM4(fal[0], aL);
        LDSM4(fal[1], aL + 16 * RSTRIDE);
        LDSM4(fbh[0][0], bH);
        LDSM4(fbh[0][1], bH + 16 * RSTRIDE);
        LDSM4(fbl[0][0], bL);
        LDSM4(fbl[0][1], bL + 16 * RSTRIDE);

#pragma unroll
        for (int p = 0; p < 4; p++) {
            const int cur = p & 1;
            const int nh  = p & 1;
            // prefetch next phase's B frags
            if (p < 3) {
                const int pn  = p + 1;
                const uint32_t bo2 = (pn >> 1) * 32 + (pn & 1) * 32 * RSTRIDE;
                LDSM4(fbh[pn & 1][0], bH + bo2);
                LDSM4(fbh[pn & 1][1], bH + bo2 + 16 * RSTRIDE);
                LDSM4(fbl[pn & 1][0], bL + bo2);
                LDSM4(fbl[pn & 1][1], bL + bo2 + 16 * RSTRIDE);
            }
#pragma unroll
            for (int mi = 0; mi < 2; mi++)
#pragma unroll
                for (int nj = 0; nj < 4; nj++)
                    mma16816(acc[mi][nh * 4 + nj], fah[mi], &fbh[cur][nj >> 1][(nj & 1) * 2]);
#pragma unroll
            for (int mi = 0; mi < 2; mi++)
#pragma unroll
                for (int nj = 0; nj < 4; nj++)
                    mma16816(acc[mi][nh * 4 + nj], fah[mi], &fbl[cur][nj >> 1][(nj & 1) * 2]);
#pragma unroll
            for (int mi = 0; mi < 2; mi++)
#pragma unroll
                for (int nj = 0; nj < 4; nj++)
                    mma16816(acc[mi][nh * 4 + nj], fal[mi], &fbh[cur][nj >> 1][(nj & 1) * 2]);
            // reload A frags for kk=1 after phase 1's MMAs
            if (p == 1) {
                LDSM4(fah[0], aH + 32);
                LDSM4(fah[1], aH + 16 * RSTRIDE + 32);
                LDSM4(fal[0], aL + 32);
                LDSM4(fal[1], aL + 16 * RSTRIDE + 32);
            }
        }
    };

    // ---- 2-stage pipelined mainloop over K=512 (16 chunks) ----
    load_chunk(0, 0);
    for (int c = 0; c < NCHUNK; c++) {
        if (c + 1 < NCHUNK) {
            load_chunk(c + 1, (c + 1) & 1);
            CPA_WAIT(1);
        } else {
            CPA_WAIT(0);
        }
        __syncthreads();
        compute_chunk(c & 1);
        __syncthreads();
    }

    // ---- epilogue ----
    const int wsel = (MODE == 0) ? (n0 >> 9) : 0;
    float* Cout = (MODE == 0) ? ((wsel == 0) ? C0 : (wsel == 1) ? C1 : C2) : C0;
    const float* bias = (MODE == 0) ? ((wsel == 0) ? b0p : (wsel == 1) ? b1p : b2p) : b0p;
    const int ncol0 = (MODE == 0) ? (n0 & 511) : n0;
    const bool fm = (MODE == 0) && (wsel < 2);

    const int g  = lane >> 2;
    const int tg = lane & 3;
#pragma unroll
    for (int mi = 0; mi < 2; mi++) {
#pragma unroll
        for (int half = 0; half < 2; half++) {
            int row = m0 + wm * 32 + mi * 16 + g + half * 8;
            float* Crow = Cout + (size_t)row * D_SZ;
            const float* Rrow = (MODE == 2) ? (resid + (size_t)row * D_SZ) : nullptr;
#pragma unroll
            for (int nj = 0; nj < 8; nj++) {
                int col = ncol0 + wn * 64 + nj * 8 + tg * 2;
                float v0 = acc[mi][nj][half * 2 + 0] + bias[col];
                float v1 = acc[mi][nj][half * 2 + 1] + bias[col + 1];
                if (MODE == 0) {
                    if (fm) {
                        v0 = (v0 > 0.f) ? (v0 + 1.f) : __expf(v0);
                        v1 = (v1 > 0.f) ? (v1 + 1.f) : __expf(v1);
                    }
                } else {
                    v0 += Rrow[col];
                    v1 += Rrow[col + 1];
                }
                *(float2*)&Crow[col] = make_float2(v0, v1);
            }
        }
    }
}

// ---------------- zero accumulators ------------------------------------------
__global__ void zero_acc_kernel()
{
    int i = blockIdx.x * blockDim.x + threadIdx.x;
    if (i < BH_SZ * HD_SZ * HD_SZ) g_kv[i] = 0.f;
    if (i < BH_SZ * HD_SZ)         g_ksum[i] = 0.f;
}

// ---------------- kv = K^T V per (b,h), plus k_sum ----------------------------
// grid: (S/256, 32) = (32, 32). 256 threads. 32-row smem tiles.
__global__ __launch_bounds__(256)
void kv_kernel()
{
    const int bh    = blockIdx.y;
    const int chunk = blockIdx.x;          // 256-row chunk
    const int b = bh >> 3, h = bh & 7;

    const float* kb = g_k + ((size_t)(b * S_SZ + chunk * 256)) * D_SZ + h * HD_SZ;
    const float* vb = g_v + ((size_t)(b * S_SZ + chunk * 256)) * D_SZ + h * HD_SZ;

    __shared__ float ks[32][64];
    __shared__ float vs[32][64];

    const int t  = threadIdx.x;
    const int dg = (t >> 4) << 2;
    const int mg = (t & 15) << 2;

    float acc[4][4];
#pragma unroll
    for (int i = 0; i < 4; i++)
#pragma unroll
        for (int j = 0; j < 4; j++) acc[i][j] = 0.f;
    float ksl = 0.f;

    for (int it = 0; it < 8; it++) {
#pragma unroll
        for (int e = t; e < 512; e += 256) {     // float4 index
            int r  = e >> 4;
            int c4 = (e & 15) << 2;
            *(float4*)&ks[r][c4] = *(const float4*)&kb[(size_t)(it * 32 + r) * D_SZ + c4];
            *(float4*)&vs[r][c4] = *(const float4*)&vb[(size_t)(it * 32 + r) * D_SZ + c4];
        }
        __syncthreads();

        if (t < 64) {
#pragma unroll
            for (int r = 0; r < 32; r++) ksl += ks[r][t];
        }
#pragma unroll
        for (int r = 0; r < 32; r++) {
            float ka[4], va[4];
            *(float4*)ka = *(float4*)&ks[r][dg];
            *(float4*)va = *(float4*)&vs[r][mg];
#pragma unroll
            for (int i = 0; i < 4; i++)
#pragma unroll
                for (int j = 0; j < 4; j++)
                    acc[i][j] = fmaf(ka[i], va[j], acc[i][j]);
        }
        __syncthreads();
    }

    float* kvdst = g_kv + bh * (HD_SZ * HD_SZ);
#pragma unroll
    for (int i = 0; i < 4; i++)
#pragma unroll
        for (int j = 0; j < 4; j++)
            atomicAdd(&kvdst[(dg + i) * HD_SZ + (mg + j)], acc[i][j]);
    if (t < 64) atomicAdd(&g_ksum[bh * HD_SZ + t], ksl);
}

// ---------------- out = (q @ kv) / max(q . ksum, 1e-6), emits bf16 hi/lo ------
__global__ __launch_bounds__(256)
void attn_kernel()
{
    const int bh   = blockIdx.y;
    const int tile = blockIdx.x;
    const int b = bh >> 3, h = bh & 7;

    __shared__ float qs[64][68];     // 68: float4-aligned + staggered banks
    __shared__ float kvb[64][64];
    __shared__ float ksb[64];
    __shared__ float nrm[64];

    const int t = threadIdx.x;
    const float* qb = g_q + ((size_t)(b * S_SZ + tile * 64)) * D_SZ + h * HD_SZ;

#pragma unroll
    for (int e = t; e < 1024; e += 256) {   // float4 tasks
        int r  = e >> 4;
        int c4 = (e & 15) << 2;
        *(float4*)&qs[r][c4] = *(const float4*)&qb[(size_t)r * D_SZ + c4];
    }
#pragma unroll
    for (int e = t; e < 1024; e += 256) {
        int r  = e >> 4;
        int c4 = (e & 15) << 2;
        *(float4*)&kvb[r][c4] = *(const float4*)&g_kv[bh * 4096 + r * 64 + c4];
    }
    if (t < 64) ksb[t] = g_ksum[bh * HD_SZ + t];
    __syncthreads();

    if (t < 64) {
        float s = 0.f;
#pragma unroll
        for (int d = 0; d < 64; d++) s = fmaf(qs[t][d], ksb[d], s);
        nrm[t] = fmaxf(s, 1e-6f);
    }
    __syncthreads();

    const int rg = (t >> 4) << 2;
    const int mg = (t & 15) << 2;
    float acc[4][4];
#pragma unroll
    for (int i = 0; i < 4; i++)
#pragma unroll
        for (int j = 0; j < 4; j++) acc[i][j] = 0.f;

#pragma unroll
    for (int kk = 0; kk < 64; kk++) {
        float a[4], bb[4];
#pragma unroll
        for (int i = 0; i < 4; i++) a[i] = qs[rg + i][kk];
        *(float4*)&bb[0] = *(float4*)&kvb[kk][mg];
#pragma unroll
        for (int i = 0; i < 4; i++)
#pragma unroll
            for (int j = 0; j < 4; j++)
                acc[i][j] = fmaf(a[i], bb[j], acc[i][j]);
    }

    size_t obase = ((size_t)(b * S_SZ + tile * 64)) * D_SZ + h * HD_SZ;
#pragma unroll
    for (int i = 0; i < 4; i++) {
        float inv = 1.0f / nrm[rg + i];
        __nv_bfloat16 hh[4], ll[4];
#pragma unroll
        for (int j = 0; j < 4; j++) {
            float v = acc[i][j] * inv;
            split2(v, hh[j], ll[j]);
        }
        size_t idx = obase + (size_t)(rg + i) * D_SZ + mg;
        *(uint2*)&g_ah[idx] = *(uint2*)hh;
        *(uint2*)&g_al[idx] = *(uint2*)ll;
    }
}

// ---------------- LayerNorm over g_y -> out (float4) --------------------------
__global__ __launch_bounds__(256)
void ln_kernel(const float* __restrict__ gamma, const float* __restrict__ beta,
               float* __restrict__ out)
{
    const int row  = blockIdx.x * 8 + (threadIdx.x >> 5);
    const int lane = threadIdx.x & 31;
    const float4* y4 = (const float4*)(g_y + (size_t)row * D_SZ);

    float4 vals[4];
    float s = 0.f, s2 = 0.f;
#pragma unroll
    for (int i = 0; i < 4; i++) {
        float4 v = y4[lane + i * 32];
        vals[i] = v;
        s += v.x + v.y + v.z + v.w;
        s2 = fmaf(v.x, v.x, s2); s2 = fmaf(v.y, v.y, s2);
        s2 = fmaf(v.z, v.z, s2); s2 = fmaf(v.w, v.w, s2);
    }
#pragma unroll
    for (int o = 16; o > 0; o >>= 1) {
        s  += __shfl_xor_sync(0xFFFFFFFFu, s, o);
        s2 += __shfl_xor_sync(0xFFFFFFFFu, s2, o);
    }
    const float mean = s * (1.0f / 512.0f);
    const float var  = s2 * (1.0f / 512.0f) - mean * mean;
    const float inv  = rsqrtf(var + 1e-5f);

    const float4* g4 = (const float4*)gamma;
    const float4* b4 = (const float4*)beta;
    float4* o4 = (float4*)(out + (size_t)row * D_SZ);
#pragma unroll
    for (int i = 0; i < 4; i++) {
        int c = lane + i * 32;
        float4 g = g4[c], bb = b4[c], v = vals[i];
        float4 r;
        r.x = (v.x - mean) * inv * g.x + bb.x;
        r.y = (v.y - mean) * inv * g.y + bb.y;
        r.z = (v.z - mean) * inv * g.z + bb.z;
        r.w = (v.w - mean) * inv * g.w + bb.w;
        o4[c] = r;
    }
}

// ---------------- launch ------------------------------------------------------
extern "C" void kernel_launch(void* const* d_in, const int* in_sizes, int n_in,
                              void* d_out, int out_size)
{
    const float* x     = (const float*)d_in[0];
    const float* Wq    = (const float*)d_in[1];
    const float* bq    = (const float*)d_in[2];
    const float* Wk    = (const float*)d_in[3];
    const float* bk    = (const float*)d_in[4];
    const float* Wv    = (const float*)d_in[5];
    const float* bv    = (const float*)d_in[6];
    const float* Wo    = (const float*)d_in[7];
    const float* bo    = (const float*)d_in[8];
    const float* gamma = (const float*)d_in[9];
    const float* beta  = (const float*)d_in[10];
    float* out = (float*)d_out;

    __nv_bfloat16 *pxh, *pxl, *pwth, *pwtl, *pah, *pal;
    float *pq, *pk, *pv, *py;
    cudaGetSymbolAddress((void**)&pxh,  g_xh);
    cudaGetSymbolAddress((void**)&pxl,  g_xl);
    cudaGetSymbolAddress((void**)&pwth, g_wth);
    cudaGetSymbolAddress((void**)&pwtl, g_wtl);
    cudaGetSymbolAddress((void**)&pah,  g_ah);
    cudaGetSymbolAddress((void**)&pal,  g_al);
    cudaGetSymbolAddress((void**)&pq,   g_q);
    cudaGetSymbolAddress((void**)&pk,   g_k);
    cudaGetSymbolAddress((void**)&pv,   g_v);
    cudaGetSymbolAddress((void**)&py,   g_y);

    const int SMEM_DYN = NSTAGE * STAGE_BYTES;   // 81920
    cudaFuncSetAttribute(gemm_tc<0>, cudaFuncAttributeMaxDynamicSharedMemorySize, SMEM_DYN);
    cudaFuncSetAttribute(gemm_tc<2>, cudaFuncAttributeMaxDynamicSharedMemorySize, SMEM_DYN);

    // split input + weights into bf16 hi/lo
    convert_x_kernel<<<(N_TOK * D_SZ / 4) / 256, 256>>>(x);
    convert_w_kernel<<<dim3(16, 16, 4), dim3(32, 32)>>>(Wq, Wk, Wv, Wo);

    // fused QKV projection: N_total = 1536 over [Wq|Wk|Wv]
    dim3 gqkv(3 * D_SZ / 128, N_TOK / 128);   // (12, 256)
    gemm_tc<0><<<gqkv, 256, SMEM_DYN>>>(pxh, pxl, pwth, pwtl,
                                        bq, bk, bv, nullptr, pq, pk, pv);

    // kv summary + k_sum
    zero_acc_kernel<<<(BH_SZ * HD_SZ * HD_SZ + 255) / 256, 256>>>();
    kv_kernel<<<dim3(S_SZ / 256, BH_SZ), 256>>>();

    // normalized attention output (emits bf16 hi/lo for the Wo GEMM)
    attn_kernel<<<dim3(S_SZ / 64, BH_SZ), 256>>>();

    // output projection + residual
    dim3 gwo(D_SZ / 128, N_TOK / 128);        // (4, 256)
    gemm_tc<2><<<gwo, 256, SMEM_DYN>>>(pah, pal, pwth + 3 * D_SZ * D_SZ,
                                       pwtl + 3 * D_SZ * D_SZ,
                                       bo, nullptr, nullptr, x, py, nullptr, nullptr);

    // layernorm
    ln_kernel<<<N_TOK / 8, 256>>>(gamma, beta, out);
}

// round 8
// speedup vs baseline: 1.0360x; 1.0360x over previous
#include <cuda_runtime.h>
#include <cuda_bf16.h>
#include <cstdint>
#include <math.h>

// Problem constants
#define B_SZ   4
#define S_SZ   8192
#define D_SZ   512
#define H_SZ   8
#define HD_SZ  64
#define N_TOK  (B_SZ * S_SZ)          // 32768
#define BH_SZ  (B_SZ * H_SZ)          // 32

// ---------------- scratch (static __device__, no allocations) ----------------
__device__ __nv_bfloat16 g_xh[(size_t)N_TOK * D_SZ];
__device__ __nv_bfloat16 g_xl[(size_t)N_TOK * D_SZ];
__device__ __nv_bfloat16 g_wth[4 * D_SZ * D_SZ];   // transposed weights, hi
__device__ __nv_bfloat16 g_wtl[4 * D_SZ * D_SZ];   // transposed weights, lo
__device__ float g_q[(size_t)N_TOK * D_SZ];
__device__ float g_k[(size_t)N_TOK * D_SZ];
__device__ float g_v[(size_t)N_TOK * D_SZ];
__device__ __nv_bfloat16 g_ah[(size_t)N_TOK * D_SZ];
__device__ __nv_bfloat16 g_al[(size_t)N_TOK * D_SZ];
__device__ float g_y[(size_t)N_TOK * D_SZ];
__device__ float g_kv[BH_SZ * HD_SZ * HD_SZ];
__device__ float g_ksum[BH_SZ * HD_SZ];

// ======================= helpers ==============================================
__device__ __forceinline__ uint32_t smem_u32(const void* p) {
    uint32_t a;
    asm("{ .reg .u64 t; cvta.to.shared.u64 t, %1; cvt.u32.u64 %0, t; }"
        : "=r"(a) : "l"(p));
    return a;
}
__device__ __forceinline__ void cpa16(uint32_t dst, const void* src) {
    asm volatile("cp.async.cg.shared.global [%0], [%1], 16;" :: "r"(dst), "l"(src));
}
#define CPA_COMMIT() asm volatile("cp.async.commit_group;" ::: "memory")
#define CPA_WAIT(n)  asm volatile("cp.async.wait_group %0;" :: "n"(n) : "memory")

#define LDSM4(r, addr)                                                          \
    asm volatile("ldmatrix.sync.aligned.m8n8.x4.shared.b16 {%0,%1,%2,%3}, [%4];"\
                 : "=r"((r)[0]), "=r"((r)[1]), "=r"((r)[2]), "=r"((r)[3])       \
                 : "r"(addr))

// HMMA: D(16x8,f32) += A(16x16,bf16,row) * B(16x8,bf16,col)
__device__ __forceinline__ void mma16816(float* d, const uint32_t* a, const uint32_t* b) {
    asm volatile(
        "mma.sync.aligned.m16n8k16.row.col.f32.bf16.bf16.f32 "
        "{%0,%1,%2,%3}, {%4,%5,%6,%7}, {%8,%9}, {%0,%1,%2,%3};"
        : "+f"(d[0]), "+f"(d[1]), "+f"(d[2]), "+f"(d[3])
        : "r"(a[0]), "r"(a[1]), "r"(a[2]), "r"(a[3]), "r"(b[0]), "r"(b[1]));
}

__device__ __forceinline__ void split2(float v, __nv_bfloat16& h, __nv_bfloat16& l) {
    h = __float2bfloat16(v);
    l = __float2bfloat16(v - __bfloat162float(h));
}

// ======================= conversion kernels ===================================
__global__ __launch_bounds__(256) void convert_x_kernel(const float* __restrict__ x)
{
    size_t i = (size_t)blockIdx.x * 256 + threadIdx.x;   // float4 index
    float4 v = ((const float4*)x)[i];
    __nv_bfloat16 h[4], l[4];
    split2(v.x, h[0], l[0]); split2(v.y, h[1], l[1]);
    split2(v.z, h[2], l[2]); split2(v.w, h[3], l[3]);
    *(uint2*)&g_xh[4 * i] = *(uint2*)h;
    *(uint2*)&g_xl[4 * i] = *(uint2*)l;
}

// transpose + split 4 weights: Wt[w][n][k] = W_w[k][n]
__global__ void convert_w_kernel(const float* __restrict__ Wq, const float* __restrict__ Wk,
                                 const float* __restrict__ Wv, const float* __restrict__ Wo)
{
    __shared__ float tile[32][33];
    const int w = blockIdx.z;
    const float* W = (w == 0) ? Wq : (w == 1) ? Wk : (w == 2) ? Wv : Wo;
    int tx = threadIdx.x, ty = threadIdx.y;
    int k = blockIdx.y * 32 + ty;
    int n = blockIdx.x * 32 + tx;
    tile[ty][tx] = W[k * D_SZ + n];
    __syncthreads();
    int nn = blockIdx.x * 32 + ty;
    int kk = blockIdx.y * 32 + tx;
    float v = tile[tx][ty];
    __nv_bfloat16 h, l;
    split2(v, h, l);
    size_t idx = (size_t)w * D_SZ * D_SZ + (size_t)nn * D_SZ + kk;
    g_wth[idx] = h;
    g_wtl[idx] = l;
}

// ======================= tensor-core GEMM (mma.sync bf16, split) ==============
// CTA tile 128x128, BK=32, 256 threads (8 warps, 4x2), warp tile 32x64.
// 2-stage cp.async pipeline; b-fragments processed in two 32-col halves.
// MODE 0: fused QKV (N_total=1536, featmap for q/k, select by n0>>9)
// MODE 2: Wo (+bias, +resid)
#define BKC     32
#define RSTRIDE 80           // bytes per smem row (32 bf16 + 16 pad)
#define A_BYTES (128 * RSTRIDE)
#define B_BYTES (128 * RSTRIDE)
#define AH_OFF  0
#define AL_OFF  (A_BYTES)
#define BH_OFF  (2 * A_BYTES)
#define BL_OFF  (2 * A_BYTES + B_BYTES)
#define STAGE_BYTES (2 * A_BYTES + 2 * B_BYTES)   // 40960
#define NSTAGE  2
#define NCHUNK  (D_SZ / BKC)                      // 16

template <int MODE>
__global__ __launch_bounds__(256, 2)
void gemm_tc(const __nv_bfloat16* __restrict__ Ah, const __nv_bfloat16* __restrict__ Al,
             const __nv_bfloat16* __restrict__ Bh, const __nv_bfloat16* __restrict__ Bl,
             const float* __restrict__ b0p, const float* __restrict__ b1p,
             const float* __restrict__ b2p, const float* __restrict__ resid,
             float* __restrict__ C0, float* __restrict__ C1, float* __restrict__ C2)
{
    extern __shared__ __align__(16) char dsm[];
    const uint32_t sb = smem_u32(dsm);

    const int t    = threadIdx.x;
    const int lane = t & 31;
    const int wid  = t >> 5;
    const int wm   = wid >> 1;          // 0..3  (32-row group)
    const int wn   = wid & 1;           // 0..1  (64-col group)
    const int m0   = blockIdx.y * 128;
    const int n0   = blockIdx.x * 128;

    float acc[2][8][4];
#pragma unroll
    for (int i = 0; i < 2; i++)
#pragma unroll
        for (int j = 0; j < 8; j++)
#pragma unroll
            for (int r = 0; r < 4; r++) acc[i][j][r] = 0.f;

    // per-lane ldmatrix address components
    const uint32_t aoff = (uint32_t)(wm * 32 + (lane & 15)) * RSTRIDE
                        + ((lane >> 4) & 1) * 16;
    const uint32_t boff = (uint32_t)(wn * 64 + (lane & 7) + ((lane >> 4) & 1) * 8) * RSTRIDE
                        + ((lane >> 3) & 1) * 16;

    // ---- async tile loader (BK=32: 64B per row, 4 x 16B parts) ----
    auto load_chunk = [&](int kc, int stage) {
        const uint32_t base = sb + stage * STAGE_BYTES;
        const size_t gkoff = (size_t)kc * BKC;
#pragma unroll
        for (int e = 0; e < 2; e++) {            // A: 128 rows x 4 parts = 512
            int id   = t + e * 256;
            int row  = id >> 2;
            int part = id & 3;
            uint32_t doff = row * RSTRIDE + part * 16;
            size_t   goff = (size_t)(m0 + row) * D_SZ + gkoff + part * 8;
            cpa16(base + AH_OFF + doff, Ah + goff);
            cpa16(base + AL_OFF + doff, Al + goff);
        }
#pragma unroll
        for (int e = 0; e < 2; e++) {            // B: 128 rows x 4 parts = 512
            int id   = t + e * 256;
            int row  = id >> 2;
            int part = id & 3;
            uint32_t doff = row * RSTRIDE + part * 16;
            size_t   goff = (size_t)(n0 + row) * D_SZ + gkoff + part * 8;
            cpa16(base + BH_OFF + doff, Bh + goff);
            cpa16(base + BL_OFF + doff, Bl + goff);
        }
        CPA_COMMIT();
    };

    // ---- compute one BK=32 chunk (2 kk steps x 2 n-halves) — R6 structure ----
    auto compute_chunk = [&](int stage) {
        const uint32_t base = sb + stage * STAGE_BYTES;
        const uint32_t aH = base + AH_OFF + aoff;
        const uint32_t aL = base + AL_OFF + aoff;
        const uint32_t bH = base + BH_OFF + boff;
        const uint32_t bL = base + BL_OFF + boff;
#pragma unroll
        for (int kk = 0; kk < 2; kk++) {
            const int cb = kk * 32;
            uint32_t fah[2][4], fal[2][4];
            LDSM4(fah[0], aH + cb);
            LDSM4(fah[1], aH + 16 * RSTRIDE + cb);
            LDSM4(fal[0], aL + cb);
            LDSM4(fal[1], aL + 16 * RSTRIDE + cb);
#pragma unroll
            for (int nh = 0; nh < 2; nh++) {
                const uint32_t bo2 = nh * 32 * RSTRIDE + cb;
                uint32_t fbh[2][4], fbl[2][4];
                LDSM4(fbh[0], bH + bo2);
                LDSM4(fbh[1], bH + bo2 + 16 * RSTRIDE);
                LDSM4(fbl[0], bL + bo2);
                LDSM4(fbl[1], bL + bo2 + 16 * RSTRIDE);
#pragma unroll
                for (int mi = 0; mi < 2; mi++)
#pragma unroll
                    for (int nj = 0; nj < 4; nj++)
                        mma16816(acc[mi][nh * 4 + nj], fah[mi], &fbh[nj >> 1][(nj & 1) * 2]);
#pragma unroll
                for (int mi = 0; mi < 2; mi++)
#pragma unroll
                    for (int nj = 0; nj < 4; nj++)
                        mma16816(acc[mi][nh * 4 + nj], fah[mi], &fbl[nj >> 1][(nj & 1) * 2]);
#pragma unroll
                for (int mi = 0; mi < 2; mi++)
#pragma unroll
                    for (int nj = 0; nj < 4; nj++)
                        mma16816(acc[mi][nh * 4 + nj], fal[mi], &fbh[nj >> 1][(nj & 1) * 2]);
            }
        }
    };

    // ---- 2-stage pipelined mainloop over K=512 (16 chunks) ----
    load_chunk(0, 0);
    for (int c = 0; c < NCHUNK; c++) {
        if (c + 1 < NCHUNK) {
            load_chunk(c + 1, (c + 1) & 1);
            CPA_WAIT(1);
        } else {
            CPA_WAIT(0);
        }
        __syncthreads();
        compute_chunk(c & 1);
        __syncthreads();
    }

    // ---- epilogue ----
    const int wsel = (MODE == 0) ? (n0 >> 9) : 0;
    float* Cout = (MODE == 0) ? ((wsel == 0) ? C0 : (wsel == 1) ? C1 : C2) : C0;
    const float* bias = (MODE == 0) ? ((wsel == 0) ? b0p : (wsel == 1) ? b1p : b2p) : b0p;
    const int ncol0 = (MODE == 0) ? (n0 & 511) : n0;
    const bool fm = (MODE == 0) && (wsel < 2);

    const int g  = lane >> 2;
    const int tg = lane & 3;
#pragma unroll
    for (int mi = 0; mi < 2; mi++) {
#pragma unroll
        for (int half = 0; half < 2; half++) {
            int row = m0 + wm * 32 + mi * 16 + g + half * 8;
            float* Crow = Cout + (size_t)row * D_SZ;
            const float* Rrow = (MODE == 2) ? (resid + (size_t)row * D_SZ) : nullptr;
#pragma unroll
            for (int nj = 0; nj < 8; nj++) {
                int col = ncol0 + wn * 64 + nj * 8 + tg * 2;
                float v0 = acc[mi][nj][half * 2 + 0] + bias[col];
                float v1 = acc[mi][nj][half * 2 + 1] + bias[col + 1];
                if (MODE == 0) {
                    if (fm) {
                        v0 = (v0 > 0.f) ? (v0 + 1.f) : __expf(v0);
                        v1 = (v1 > 0.f) ? (v1 + 1.f) : __expf(v1);
                    }
                } else {
                    v0 += Rrow[col];
                    v1 += Rrow[col + 1];
                }
                *(float2*)&Crow[col] = make_float2(v0, v1);
            }
        }
    }
}

// ---------------- zero accumulators ------------------------------------------
__global__ void zero_acc_kernel()
{
    int i = blockIdx.x * blockDim.x + threadIdx.x;
    if (i < BH_SZ * HD_SZ * HD_SZ) g_kv[i] = 0.f;
    if (i < BH_SZ * HD_SZ)         g_ksum[i] = 0.f;
}

// ---------------- kv = K^T V per (b,h), plus k_sum ----------------------------
// grid: (S/256, 32) = (32, 32). 256 threads. 32-row smem tiles.
__global__ __launch_bounds__(256)
void kv_kernel()
{
    const int bh    = blockIdx.y;
    const int chunk = blockIdx.x;          // 256-row chunk
    const int b = bh >> 3, h = bh & 7;

    const float* kb = g_k + ((size_t)(b * S_SZ + chunk * 256)) * D_SZ + h * HD_SZ;
    const float* vb = g_v + ((size_t)(b * S_SZ + chunk * 256)) * D_SZ + h * HD_SZ;

    __shared__ float ks[32][64];
    __shared__ float vs[32][64];

    const int t  = threadIdx.x;
    const int dg = (t >> 4) << 2;
    const int mg = (t & 15) << 2;

    float acc[4][4];
#pragma unroll
    for (int i = 0; i < 4; i++)
#pragma unroll
        for (int j = 0; j < 4; j++) acc[i][j] = 0.f;
    float ksl = 0.f;

    for (int it = 0; it < 8; it++) {
#pragma unroll
        for (int e = t; e < 512; e += 256) {     // float4 index
            int r  = e >> 4;
            int c4 = (e & 15) << 2;
            *(float4*)&ks[r][c4] = *(const float4*)&kb[(size_t)(it * 32 + r) * D_SZ + c4];
            *(float4*)&vs[r][c4] = *(const float4*)&vb[(size_t)(it * 32 + r) * D_SZ + c4];
        }
        __syncthreads();

        if (t < 64) {
#pragma unroll
            for (int r = 0; r < 32; r++) ksl += ks[r][t];
        }
#pragma unroll
        for (int r = 0; r < 32; r++) {
            float ka[4], va[4];
            *(float4*)ka = *(float4*)&ks[r][dg];
            *(float4*)va = *(float4*)&vs[r][mg];
#pragma unroll
            for (int i = 0; i < 4; i++)
#pragma unroll
                for (int j = 0; j < 4; j++)
                    acc[i][j] = fmaf(ka[i], va[j], acc[i][j]);
        }
        __syncthreads();
    }

    float* kvdst = g_kv + bh * (HD_SZ * HD_SZ);
#pragma unroll
    for (int i = 0; i < 4; i++)
#pragma unroll
        for (int j = 0; j < 4; j++)
            atomicAdd(&kvdst[(dg + i) * HD_SZ + (mg + j)], acc[i][j]);
    if (t < 64) atomicAdd(&g_ksum[bh * HD_SZ + t], ksl);
}

// ---------------- out = (q @ kv) / max(q . ksum, 1e-6), emits bf16 hi/lo ------
__global__ __launch_bounds__(256)
void attn_kernel()
{
    const int bh   = blockIdx.y;
    const int tile = blockIdx.x;
    const int b = bh >> 3, h = bh & 7;

    __shared__ float qs[64][68];     // 68: float4-aligned + staggered banks
    __shared__ float kvb[64][64];
    __shared__ float ksb[64];
    __shared__ float nrm[64];

    const int t = threadIdx.x;
    const float* qb = g_q + ((size_t)(b * S_SZ + tile * 64)) * D_SZ + h * HD_SZ;

#pragma unroll
    for (int e = t; e < 1024; e += 256) {   // float4 tasks
        int r  = e >> 4;
        int c4 = (e & 15) << 2;
        *(float4*)&qs[r][c4] = *(const float4*)&qb[(size_t)r * D_SZ + c4];
    }
#pragma unroll
    for (int e = t; e < 1024; e += 256) {
        int r  = e >> 4;
        int c4 = (e & 15) << 2;
        *(float4*)&kvb[r][c4] = *(const float4*)&g_kv[bh * 4096 + r * 64 + c4];
    }
    if (t < 64) ksb[t] = g_ksum[bh * HD_SZ + t];
    __syncthreads();

    if (t < 64) {
        float s = 0.f;
#pragma unroll
        for (int d = 0; d < 64; d++) s = fmaf(qs[t][d], ksb[d], s);
        nrm[t] = fmaxf(s, 1e-6f);
    }
    __syncthreads();

    const int rg = (t >> 4) << 2;
    const int mg = (t & 15) << 2;
    float acc[4][4];
#pragma unroll
    for (int i = 0; i < 4; i++)
#pragma unroll
        for (int j = 0; j < 4; j++) acc[i][j] = 0.f;

#pragma unroll
    for (int kk = 0; kk < 64; kk++) {
        float a[4], bb[4];
#pragma unroll
        for (int i = 0; i < 4; i++) a[i] = qs[rg + i][kk];
        *(float4*)&bb[0] = *(float4*)&kvb[kk][mg];
#pragma unroll
        for (int i = 0; i < 4; i++)
#pragma unroll
            for (int j = 0; j < 4; j++)
                acc[i][j] = fmaf(a[i], bb[j], acc[i][j]);
    }

    size_t obase = ((size_t)(b * S_SZ + tile * 64)) * D_SZ + h * HD_SZ;
#pragma unroll
    for (int i = 0; i < 4; i++) {
        float inv = 1.0f / nrm[rg + i];
        __nv_bfloat16 hh[4], ll[4];
#pragma unroll
        for (int j = 0; j < 4; j++) {
            float v = acc[i][j] * inv;
            split2(v, hh[j], ll[j]);
        }
        size_t idx = obase + (size_t)(rg + i) * D_SZ + mg;
        *(uint2*)&g_ah[idx] = *(uint2*)hh;
        *(uint2*)&g_al[idx] = *(uint2*)ll;
    }
}

// ---------------- LayerNorm over g_y -> out (float4) --------------------------
__global__ __launch_bounds__(256)
void ln_kernel(const float* __restrict__ gamma, const float* __restrict__ beta,
               float* __restrict__ out)
{
    const int row  = blockIdx.x * 8 + (threadIdx.x >> 5);
    const int lane = threadIdx.x & 31;
    const float4* y4 = (const float4*)(g_y + (size_t)row * D_SZ);

    float4 vals[4];
    float s = 0.f, s2 = 0.f;
#pragma unroll
    for (int i = 0; i < 4; i++) {
        float4 v = y4[lane + i * 32];
        vals[i] = v;
        s += v.x + v.y + v.z + v.w;
        s2 = fmaf(v.x, v.x, s2); s2 = fmaf(v.y, v.y, s2);
        s2 = fmaf(v.z, v.z, s2); s2 = fmaf(v.w, v.w, s2);
    }
#pragma unroll
    for (int o = 16; o > 0; o >>= 1) {
        s  += __shfl_xor_sync(0xFFFFFFFFu, s, o);
        s2 += __shfl_xor_sync(0xFFFFFFFFu, s2, o);
    }
    const float mean = s * (1.0f / 512.0f);
    const float var  = s2 * (1.0f / 512.0f) - mean * mean;
    const float inv  = rsqrtf(var + 1e-5f);

    const float4* g4 = (const float4*)gamma;
    const float4* b4 = (const float4*)beta;
    float4* o4 = (float4*)(out + (size_t)row * D_SZ);
#pragma unroll
    for (int i = 0; i < 4; i++) {
        int c = lane + i * 32;
        float4 g = g4[c], bb = b4[c], v = vals[i];
        float4 r;
        r.x = (v.x - mean) * inv * g.x + bb.x;
        r.y = (v.y - mean) * inv * g.y + bb.y;
        r.z = (v.z - mean) * inv * g.z + bb.z;
        r.w = (v.w - mean) * inv * g.w + bb.w;
        o4[c] = r;
    }
}

// ---------------- launch ------------------------------------------------------
extern "C" void kernel_launch(void* const* d_in, const int* in_sizes, int n_in,
                              void* d_out, int out_size)
{
    const float* x     = (const float*)d_in[0];
    const float* Wq    = (const float*)d_in[1];
    const float* bq    = (const float*)d_in[2];
    const float* Wk    = (const float*)d_in[3];
    const float* bk    = (const float*)d_in[4];
    const float* Wv    = (const float*)d_in[5];
    const float* bv    = (const float*)d_in[6];
    const float* Wo    = (const float*)d_in[7];
    const float* bo    = (const float*)d_in[8];
    const float* gamma = (const float*)d_in[9];
    const float* beta  = (const float*)d_in[10];
    float* out = (float*)d_out;

    __nv_bfloat16 *pxh, *pxl, *pwth, *pwtl, *pah, *pal;
    float *pq, *pk, *pv, *py;
    cudaGetSymbolAddress((void**)&pxh,  g_xh);
    cudaGetSymbolAddress((void**)&pxl,  g_xl);
    cudaGetSymbolAddress((void**)&pwth, g_wth);
    cudaGetSymbolAddress((void**)&pwtl, g_wtl);
    cudaGetSymbolAddress((void**)&pah,  g_ah);
    cudaGetSymbolAddress((void**)&pal,  g_al);
    cudaGetSymbolAddress((void**)&pq,   g_q);
    cudaGetSymbolAddress((void**)&pk,   g_k);
    cudaGetSymbolAddress((void**)&pv,   g_v);
    cudaGetSymbolAddress((void**)&py,   g_y);

    const int SMEM_DYN = NSTAGE * STAGE_BYTES;   // 81920
    cudaFuncSetAttribute(gemm_tc<0>, cudaFuncAttributeMaxDynamicSharedMemorySize, SMEM_DYN);
    cudaFuncSetAttribute(gemm_tc<2>, cudaFuncAttributeMaxDynamicSharedMemorySize, SMEM_DYN);

    // split input + weights into bf16 hi/lo
    convert_x_kernel<<<(N_TOK * D_SZ / 4) / 256, 256>>>(x);
    convert_w_kernel<<<dim3(16, 16, 4), dim3(32, 32)>>>(Wq, Wk, Wv, Wo);

    // fused QKV projection: N_total = 1536 over [Wq|Wk|Wv]
    dim3 gqkv(3 * D_SZ / 128, N_TOK / 128);   // (12, 256)
    gemm_tc<0><<<gqkv, 256, SMEM_DYN>>>(pxh, pxl, pwth, pwtl,
                                        bq, bk, bv, nullptr, pq, pk, pv);

    // kv summary + k_sum
    zero_acc_kernel<<<(BH_SZ * HD_SZ * HD_SZ + 255) / 256, 256>>>();
    kv_kernel<<<dim3(S_SZ / 256, BH_SZ), 256>>>();

    // normalized attention output (emits bf16 hi/lo for the Wo GEMM)
    attn_kernel<<<dim3(S_SZ / 64, BH_SZ), 256>>>();

    // output projection + residual
    dim3 gwo(D_SZ / 128, N_TOK / 128);        // (4, 256)
    gemm_tc<2><<<gwo, 256, SMEM_DYN>>>(pah, pal, pwth + 3 * D_SZ * D_SZ,
                                       pwtl + 3 * D_SZ * D_SZ,
                                       bo, nullptr, nullptr, x, py, nullptr, nullptr);

    // layernorm
    ln_kernel<<<N_TOK / 8, 256>>>(gamma, beta, out);
}

// round 9
// speedup vs baseline: 1.3030x; 1.2577x over previous
#include <cuda_runtime.h>
#include <cuda_fp16.h>
#include <cstdint>
#include <math.h>

// Problem constants
#define B_SZ   4
#define S_SZ   8192
#define D_SZ   512
#define H_SZ   8
#define HD_SZ  64
#define N_TOK  (B_SZ * S_SZ)          // 32768
#define BH_SZ  (B_SZ * H_SZ)          // 32

// ---------------- scratch (static __device__, no allocations) ----------------
__device__ __half g_xh[(size_t)N_TOK * D_SZ];
__device__ __half g_xl[(size_t)N_TOK * D_SZ];
__device__ __half g_wt[4 * D_SZ * D_SZ];          // transposed weights, fp16
__device__ float g_q[(size_t)N_TOK * D_SZ];
__device__ float g_k[(size_t)N_TOK * D_SZ];
__device__ float g_v[(size_t)N_TOK * D_SZ];
__device__ __half g_ah[(size_t)N_TOK * D_SZ];
__device__ __half g_al[(size_t)N_TOK * D_SZ];
__device__ float g_y[(size_t)N_TOK * D_SZ];
__device__ float g_kv[BH_SZ * HD_SZ * HD_SZ];
__device__ float g_ksum[BH_SZ * HD_SZ];

// ======================= helpers ==============================================
__device__ __forceinline__ uint32_t smem_u32(const void* p) {
    uint32_t a;
    asm("{ .reg .u64 t; cvta.to.shared.u64 t, %1; cvt.u32.u64 %0, t; }"
        : "=r"(a) : "l"(p));
    return a;
}
__device__ __forceinline__ void cpa16(uint32_t dst, const void* src) {
    asm volatile("cp.async.cg.shared.global [%0], [%1], 16;" :: "r"(dst), "l"(src));
}
#define CPA_COMMIT() asm volatile("cp.async.commit_group;" ::: "memory")
#define CPA_WAIT(n)  asm volatile("cp.async.wait_group %0;" :: "n"(n) : "memory")

#define LDSM4(r, addr)                                                          \
    asm volatile("ldmatrix.sync.aligned.m8n8.x4.shared.b16 {%0,%1,%2,%3}, [%4];"\
                 : "=r"((r)[0]), "=r"((r)[1]), "=r"((r)[2]), "=r"((r)[3])       \
                 : "r"(addr))

// HMMA: D(16x8,f32) += A(16x16,f16,row) * B(16x8,f16,col)
__device__ __forceinline__ void mma16816(float* d, const uint32_t* a, const uint32_t* b) {
    asm volatile(
        "mma.sync.aligned.m16n8k16.row.col.f32.f16.f16.f32 "
        "{%0,%1,%2,%3}, {%4,%5,%6,%7}, {%8,%9}, {%0,%1,%2,%3};"
        : "+f"(d[0]), "+f"(d[1]), "+f"(d[2]), "+f"(d[3])
        : "r"(a[0]), "r"(a[1]), "r"(a[2]), "r"(a[3]), "r"(b[0]), "r"(b[1]));
}

__device__ __forceinline__ void split2h(float v, __half& h, __half& l) {
    h = __float2half(v);
    l = __float2half(v - __half2float(h));
}

// ======================= conversion kernels ===================================
// also zeroes the kv/ksum accumulators (merged zero_acc)
__global__ __launch_bounds__(256) void convert_x_kernel(const float* __restrict__ x)
{
    size_t i = (size_t)blockIdx.x * 256 + threadIdx.x;   // float4 index
    float4 v = ((const float4*)x)[i];
    __half h[4], l[4];
    split2h(v.x, h[0], l[0]); split2h(v.y, h[1], l[1]);
    split2h(v.z, h[2], l[2]); split2h(v.w, h[3], l[3]);
    *(uint2*)&g_xh[4 * i] = *(uint2*)h;
    *(uint2*)&g_xl[4 * i] = *(uint2*)l;
    if (i < BH_SZ * HD_SZ * HD_SZ) g_kv[i] = 0.f;
    if (i < BH_SZ * HD_SZ)         g_ksum[i] = 0.f;
}

// transpose 4 weights to fp16: Wt[w][n][k] = W_w[k][n]
__global__ void convert_w_kernel(const float* __restrict__ Wq, const float* __restrict__ Wk,
                                 const float* __restrict__ Wv, const float* __restrict__ Wo)
{
    __shared__ float tile[32][33];
    const int w = blockIdx.z;
    const float* W = (w == 0) ? Wq : (w == 1) ? Wk : (w == 2) ? Wv : Wo;
    int tx = threadIdx.x, ty = threadIdx.y;
    int k = blockIdx.y * 32 + ty;
    int n = blockIdx.x * 32 + tx;
    tile[ty][tx] = W[k * D_SZ + n];
    __syncthreads();
    int nn = blockIdx.x * 32 + ty;
    int kk = blockIdx.y * 32 + tx;
    float v = tile[tx][ty];
    size_t idx = (size_t)w * D_SZ * D_SZ + (size_t)nn * D_SZ + kk;
    g_wt[idx] = __float2half(v);
}

// ======================= tensor-core GEMM (mma.sync fp16, A-split) ============
// CTA tile 128x128, BK=32, 256 threads (8 warps, 4x2), warp tile 32x64.
// 2-stage cp.async pipeline; D = Ah*B + Al*B (A split fp16, B single fp16).
// MODE 0: fused QKV (N_total=1536, featmap for q/k, select by n0>>9)
// MODE 2: Wo (+bias, +resid)
#define BKC     32
#define RSTRIDE 80           // bytes per smem row (32 fp16 + 16 pad)
#define A_BYTES (128 * RSTRIDE)
#define B_BYTES (128 * RSTRIDE)
#define AH_OFF  0
#define AL_OFF  (A_BYTES)
#define BH_OFF  (2 * A_BYTES)
#define STAGE_BYTES (2 * A_BYTES + B_BYTES)       // 30720
#define NSTAGE  2
#define NCHUNK  (D_SZ / BKC)                      // 16

template <int MODE>
__global__ __launch_bounds__(256, 2)
void gemm_tc(const __half* __restrict__ Ah, const __half* __restrict__ Al,
             const __half* __restrict__ Bh,
             const float* __restrict__ b0p, const float* __restrict__ b1p,
             const float* __restrict__ b2p, const float* __restrict__ resid,
             float* __restrict__ C0, float* __restrict__ C1, float* __restrict__ C2)
{
    extern __shared__ __align__(16) char dsm[];
    const uint32_t sb = smem_u32(dsm);

    const int t    = threadIdx.x;
    const int lane = t & 31;
    const int wid  = t >> 5;
    const int wm   = wid >> 1;          // 0..3  (32-row group)
    const int wn   = wid & 1;           // 0..1  (64-col group)
    const int m0   = blockIdx.y * 128;
    const int n0   = blockIdx.x * 128;

    float acc[2][8][4];
#pragma unroll
    for (int i = 0; i < 2; i++)
#pragma unroll
        for (int j = 0; j < 8; j++)
#pragma unroll
            for (int r = 0; r < 4; r++) acc[i][j][r] = 0.f;

    // per-lane ldmatrix address components
    const uint32_t aoff = (uint32_t)(wm * 32 + (lane & 15)) * RSTRIDE
                        + ((lane >> 4) & 1) * 16;
    const uint32_t boff = (uint32_t)(wn * 64 + (lane & 7) + ((lane >> 4) & 1) * 8) * RSTRIDE
                        + ((lane >> 3) & 1) * 16;

    // ---- async tile loader (BK=32: 64B per row, 4 x 16B parts) ----
    auto load_chunk = [&](int kc, int stage) {
        const uint32_t base = sb + stage * STAGE_BYTES;
        const size_t gkoff = (size_t)kc * BKC;
#pragma unroll
        for (int e = 0; e < 2; e++) {            // A: 128 rows x 4 parts = 512
            int id   = t + e * 256;
            int row  = id >> 2;
            int part = id & 3;
            uint32_t doff = row * RSTRIDE + part * 16;
            size_t   goff = (size_t)(m0 + row) * D_SZ + gkoff + part * 8;
            cpa16(base + AH_OFF + doff, Ah + goff);
            cpa16(base + AL_OFF + doff, Al + goff);
        }
#pragma unroll
        for (int e = 0; e < 2; e++) {            // B: 128 rows x 4 parts = 512
            int id   = t + e * 256;
            int row  = id >> 2;
            int part = id & 3;
            uint32_t doff = row * RSTRIDE + part * 16;
            size_t   goff = (size_t)(n0 + row) * D_SZ + gkoff + part * 8;
            cpa16(base + BH_OFF + doff, Bh + goff);
        }
        CPA_COMMIT();
    };

    // ---- compute one BK=32 chunk (2 kk steps x 2 n-halves) ----
    auto compute_chunk = [&](int stage) {
        const uint32_t base = sb + stage * STAGE_BYTES;
        const uint32_t aH = base + AH_OFF + aoff;
        const uint32_t aL = base + AL_OFF + aoff;
        const uint32_t bH = base + BH_OFF + boff;
#pragma unroll
        for (int kk = 0; kk < 2; kk++) {
            const int cb = kk * 32;
            uint32_t fah[2][4], fal[2][4];
            LDSM4(fah[0], aH + cb);
            LDSM4(fah[1], aH + 16 * RSTRIDE + cb);
            LDSM4(fal[0], aL + cb);
            LDSM4(fal[1], aL + 16 * RSTRIDE + cb);
#pragma unroll
            for (int nh = 0; nh < 2; nh++) {
                const uint32_t bo2 = nh * 32 * RSTRIDE + cb;
                uint32_t fbh[2][4];
                LDSM4(fbh[0], bH + bo2);
                LDSM4(fbh[1], bH + bo2 + 16 * RSTRIDE);
#pragma unroll
                for (int mi = 0; mi < 2; mi++)
#pragma unroll
                    for (int nj = 0; nj < 4; nj++)
                        mma16816(acc[mi][nh * 4 + nj], fah[mi], &fbh[nj >> 1][(nj & 1) * 2]);
#pragma unroll
                for (int mi = 0; mi < 2; mi++)
#pragma unroll
                    for (int nj = 0; nj < 4; nj++)
                        mma16816(acc[mi][nh * 4 + nj], fal[mi], &fbh[nj >> 1][(nj & 1) * 2]);
            }
        }
    };

    // ---- 2-stage pipelined mainloop over K=512 (16 chunks) ----
    load_chunk(0, 0);
    for (int c = 0; c < NCHUNK; c++) {
        if (c + 1 < NCHUNK) {
            load_chunk(c + 1, (c + 1) & 1);
            CPA_WAIT(1);
        } else {
            CPA_WAIT(0);
        }
        __syncthreads();
        compute_chunk(c & 1);
        __syncthreads();
    }

    // ---- epilogue ----
    const int wsel = (MODE == 0) ? (n0 >> 9) : 0;
    float* Cout = (MODE == 0) ? ((wsel == 0) ? C0 : (wsel == 1) ? C1 : C2) : C0;
    const float* bias = (MODE == 0) ? ((wsel == 0) ? b0p : (wsel == 1) ? b1p : b2p) : b0p;
    const int ncol0 = (MODE == 0) ? (n0 & 511) : n0;
    const bool fm = (MODE == 0) && (wsel < 2);

    const int g  = lane >> 2;
    const int tg = lane & 3;
#pragma unroll
    for (int mi = 0; mi < 2; mi++) {
#pragma unroll
        for (int half = 0; half < 2; half++) {
            int row = m0 + wm * 32 + mi * 16 + g + half * 8;
            float* Crow = Cout + (size_t)row * D_SZ;
            const float* Rrow = (MODE == 2) ? (resid + (size_t)row * D_SZ) : nullptr;
#pragma unroll
            for (int nj = 0; nj < 8; nj++) {
                int col = ncol0 + wn * 64 + nj * 8 + tg * 2;
                float v0 = acc[mi][nj][half * 2 + 0] + bias[col];
                float v1 = acc[mi][nj][half * 2 + 1] + bias[col + 1];
                if (MODE == 0) {
                    if (fm) {
                        v0 = (v0 > 0.f) ? (v0 + 1.f) : __expf(v0);
                        v1 = (v1 > 0.f) ? (v1 + 1.f) : __expf(v1);
                    }
                } else {
                    v0 += Rrow[col];
                    v1 += Rrow[col + 1];
                }
                *(float2*)&Crow[col] = make_float2(v0, v1);
            }
        }
    }
}

// ---------------- kv = K^T V per (b,h), plus k_sum ----------------------------
// grid: (S/256, 32) = (32, 32). 256 threads. 32-row smem tiles.
__global__ __launch_bounds__(256)
void kv_kernel()
{
    const int bh    = blockIdx.y;
    const int chunk = blockIdx.x;          // 256-row chunk
    const int b = bh >> 3, h = bh & 7;

    const float* kb = g_k + ((size_t)(b * S_SZ + chunk * 256)) * D_SZ + h * HD_SZ;
    const float* vb = g_v + ((size_t)(b * S_SZ + chunk * 256)) * D_SZ + h * HD_SZ;

    __shared__ float ks[32][64];
    __shared__ float vs[32][64];

    const int t  = threadIdx.x;
    const int dg = (t >> 4) << 2;
    const int mg = (t & 15) << 2;

    float acc[4][4];
#pragma unroll
    for (int i = 0; i < 4; i++)
#pragma unroll
        for (int j = 0; j < 4; j++) acc[i][j] = 0.f;
    float ksl = 0.f;

    for (int it = 0; it < 8; it++) {
#pragma unroll
        for (int e = t; e < 512; e += 256) {     // float4 index
            int r  = e >> 4;
            int c4 = (e & 15) << 2;
            *(float4*)&ks[r][c4] = *(const float4*)&kb[(size_t)(it * 32 + r) * D_SZ + c4];
            *(float4*)&vs[r][c4] = *(const float4*)&vb[(size_t)(it * 32 + r) * D_SZ + c4];
        }
        __syncthreads();

        if (t < 64) {
#pragma unroll
            for (int r = 0; r < 32; r++) ksl += ks[r][t];
        }
#pragma unroll
        for (int r = 0; r < 32; r++) {
            float ka[4], va[4];
            *(float4*)ka = *(float4*)&ks[r][dg];
            *(float4*)va = *(float4*)&vs[r][mg];
#pragma unroll
            for (int i = 0; i < 4; i++)
#pragma unroll
                for (int j = 0; j < 4; j++)
                    acc[i][j] = fmaf(ka[i], va[j], acc[i][j]);
        }
        __syncthreads();
    }

    float* kvdst = g_kv + bh * (HD_SZ * HD_SZ);
#pragma unroll
    for (int i = 0; i < 4; i++)
#pragma unroll
        for (int j = 0; j < 4; j++)
            atomicAdd(&kvdst[(dg + i) * HD_SZ + (mg + j)], acc[i][j]);
    if (t < 64) atomicAdd(&g_ksum[bh * HD_SZ + t], ksl);
}

// ---------------- out = (q @ kv) / max(q . ksum, 1e-6), emits fp16 hi/lo ------
__global__ __launch_bounds__(256)
void attn_kernel()
{
    const int bh   = blockIdx.y;
    const int tile = blockIdx.x;
    const int b = bh >> 3, h = bh & 7;

    __shared__ float qs[64][68];     // 68: float4-aligned + staggered banks
    __shared__ float kvb[64][64];
    __shared__ float ksb[64];
    __shared__ float nrm[64];

    const int t = threadIdx.x;
    const float* qb = g_q + ((size_t)(b * S_SZ + tile * 64)) * D_SZ + h * HD_SZ;

#pragma unroll
    for (int e = t; e < 1024; e += 256) {   // float4 tasks
        int r  = e >> 4;
        int c4 = (e & 15) << 2;
        *(float4*)&qs[r][c4] = *(const float4*)&qb[(size_t)r * D_SZ + c4];
    }
#pragma unroll
    for (int e = t; e < 1024; e += 256) {
        int r  = e >> 4;
        int c4 = (e & 15) << 2;
        *(float4*)&kvb[r][c4] = *(const float4*)&g_kv[bh * 4096 + r * 64 + c4];
    }
    if (t < 64) ksb[t] = g_ksum[bh * HD_SZ + t];
    __syncthreads();

    if (t < 64) {
        float s = 0.f;
#pragma unroll
        for (int d = 0; d < 64; d++) s = fmaf(qs[t][d], ksb[d], s);
        nrm[t] = fmaxf(s, 1e-6f);
    }
    __syncthreads();

    const int rg = (t >> 4) << 2;
    const int mg = (t & 15) << 2;
    float acc[4][4];
#pragma unroll
    for (int i = 0; i < 4; i++)
#pragma unroll
        for (int j = 0; j < 4; j++) acc[i][j] = 0.f;

#pragma unroll
    for (int kk = 0; kk < 64; kk++) {
        float a[4], bb[4];
#pragma unroll
        for (int i = 0; i < 4; i++) a[i] = qs[rg + i][kk];
        *(float4*)&bb[0] = *(float4*)&kvb[kk][mg];
#pragma unroll
        for (int i = 0; i < 4; i++)
#pragma unroll
            for (int j = 0; j < 4; j++)
                acc[i][j] = fmaf(a[i], bb[j], acc[i][j]);
    }

    size_t obase = ((size_t)(b * S_SZ + tile * 64)) * D_SZ + h * HD_SZ;
#pragma unroll
    for (int i = 0; i < 4; i++) {
        float inv = 1.0f / nrm[rg + i];
        __half hh[4], ll[4];
#pragma unroll
        for (int j = 0; j < 4; j++) {
            float v = acc[i][j] * inv;
            split2h(v, hh[j], ll[j]);
        }
        size_t idx = obase + (size_t)(rg + i) * D_SZ + mg;
        *(uint2*)&g_ah[idx] = *(uint2*)hh;
        *(uint2*)&g_al[idx] = *(uint2*)ll;
    }
}

// ---------------- LayerNorm over g_y -> out (float4) --------------------------
__global__ __launch_bounds__(256)
void ln_kernel(const float* __restrict__ gamma, const float* __restrict__ beta,
               float* __restrict__ out)
{
    const int row  = blockIdx.x * 8 + (threadIdx.x >> 5);
    const int lane = threadIdx.x & 31;
    const float4* y4 = (const float4*)(g_y + (size_t)row * D_SZ);

    float4 vals[4];
    float s = 0.f, s2 = 0.f;
#pragma unroll
    for (int i = 0; i < 4; i++) {
        float4 v = y4[lane + i * 32];
        vals[i] = v;
        s += v.x + v.y + v.z + v.w;
        s2 = fmaf(v.x, v.x, s2); s2 = fmaf(v.y, v.y, s2);
        s2 = fmaf(v.z, v.z, s2); s2 = fmaf(v.w, v.w, s2);
    }
#pragma unroll
    for (int o = 16; o > 0; o >>= 1) {
        s  += __shfl_xor_sync(0xFFFFFFFFu, s, o);
        s2 += __shfl_xor_sync(0xFFFFFFFFu, s2, o);
    }
    const float mean = s * (1.0f / 512.0f);
    const float var  = s2 * (1.0f / 512.0f) - mean * mean;
    const float inv  = rsqrtf(var + 1e-5f);

    const float4* g4 = (const float4*)gamma;
    const float4* b4 = (const float4*)beta;
    float4* o4 = (float4*)(out + (size_t)row * D_SZ);
#pragma unroll
    for (int i = 0; i < 4; i++) {
        int c = lane + i * 32;
        float4 g = g4[c], bb = b4[c], v = vals[i];
        float4 r;
        r.x = (v.x - mean) * inv * g.x + bb.x;
        r.y = (v.y - mean) * inv * g.y + bb.y;
        r.z = (v.z - mean) * inv * g.z + bb.z;
        r.w = (v.w - mean) * inv * g.w + bb.w;
        o4[c] = r;
    }
}

// ---------------- launch ------------------------------------------------------
extern "C" void kernel_launch(void* const* d_in, const int* in_sizes, int n_in,
                              void* d_out, int out_size)
{
    const float* x     = (const float*)d_in[0];
    const float* Wq    = (const float*)d_in[1];
    const float* bq    = (const float*)d_in[2];
    const float* Wk    = (const float*)d_in[3];
    const float* bk    = (const float*)d_in[4];
    const float* Wv    = (const float*)d_in[5];
    const float* bv    = (const float*)d_in[6];
    const float* Wo    = (const float*)d_in[7];
    const float* bo    = (const float*)d_in[8];
    const float* gamma = (const float*)d_in[9];
    const float* beta  = (const float*)d_in[10];
    float* out = (float*)d_out;

    __half *pxh, *pxl, *pwt, *pah, *pal;
    float *pq, *pk, *pv, *py;
    cudaGetSymbolAddress((void**)&pxh, g_xh);
    cudaGetSymbolAddress((void**)&pxl, g_xl);
    cudaGetSymbolAddress((void**)&pwt, g_wt);
    cudaGetSymbolAddress((void**)&pah, g_ah);
    cudaGetSymbolAddress((void**)&pal, g_al);
    cudaGetSymbolAddress((void**)&pq,  g_q);
    cudaGetSymbolAddress((void**)&pk,  g_k);
    cudaGetSymbolAddress((void**)&pv,  g_v);
    cudaGetSymbolAddress((void**)&py,  g_y);

    const int SMEM_DYN = NSTAGE * STAGE_BYTES;   // 61440
    cudaFuncSetAttribute(gemm_tc<0>, cudaFuncAttributeMaxDynamicSharedMemorySize, SMEM_DYN);
    cudaFuncSetAttribute(gemm_tc<2>, cudaFuncAttributeMaxDynamicSharedMemorySize, SMEM_DYN);

    // split input into fp16 hi/lo (+ zero kv/ksum accumulators), weights to fp16
    convert_x_kernel<<<(N_TOK * D_SZ / 4) / 256, 256>>>(x);
    convert_w_kernel<<<dim3(16, 16, 4), dim3(32, 32)>>>(Wq, Wk, Wv, Wo);

    // fused QKV projection: N_total = 1536 over [Wq|Wk|Wv]
    dim3 gqkv(3 * D_SZ / 128, N_TOK / 128);   // (12, 256)
    gemm_tc<0><<<gqkv, 256, SMEM_DYN>>>(pxh, pxl, pwt,
                                        bq, bk, bv, nullptr, pq, pk, pv);

    // kv summary + k_sum
    kv_kernel<<<dim3(S_SZ / 256, BH_SZ), 256>>>();

    // normalized attention output (emits fp16 hi/lo for the Wo GEMM)
    attn_kernel<<<dim3(S_SZ / 64, BH_SZ), 256>>>();

    // output projection + residual
    dim3 gwo(D_SZ / 128, N_TOK / 128);        // (4, 256)
    gemm_tc<2><<<gwo, 256, SMEM_DYN>>>(pah, pal, pwt + 3 * D_SZ * D_SZ,
                                       bo, nullptr, nullptr, x, py, nullptr, nullptr);

    // layernorm
    ln_kernel<<<N_TOK / 8, 256>>>(gamma, beta, out);
}

// round 10
// speedup vs baseline: 1.3778x; 1.0574x over previous
#include <cuda_runtime.h>
#include <cuda_fp16.h>
#include <cstdint>
#include <math.h>

// Problem constants
#define B_SZ   4
#define S_SZ   8192
#define D_SZ   512
#define H_SZ   8
#define HD_SZ  64
#define N_TOK  (B_SZ * S_SZ)          // 32768
#define BH_SZ  (B_SZ * H_SZ)          // 32

// ---------------- scratch (static __device__, no allocations) ----------------
__device__ __half g_xh[(size_t)N_TOK * D_SZ];
__device__ __half g_xl[(size_t)N_TOK * D_SZ];
__device__ __half g_wt[4 * D_SZ * D_SZ];          // transposed weights, fp16
__device__ float  g_q[(size_t)N_TOK * D_SZ];
__device__ __half g_kh[(size_t)N_TOK * D_SZ];     // feature-mapped k, hi/lo
__device__ __half g_kl[(size_t)N_TOK * D_SZ];
__device__ __half g_vh[(size_t)N_TOK * D_SZ];     // v, hi/lo
__device__ __half g_vl[(size_t)N_TOK * D_SZ];
__device__ __half g_ah[(size_t)N_TOK * D_SZ];
__device__ __half g_al[(size_t)N_TOK * D_SZ];
__device__ float  g_y[(size_t)N_TOK * D_SZ];
__device__ float  g_kv[BH_SZ * HD_SZ * HD_SZ];
__device__ float  g_ksum[BH_SZ * HD_SZ];

// ======================= helpers ==============================================
__device__ __forceinline__ uint32_t smem_u32(const void* p) {
    uint32_t a;
    asm("{ .reg .u64 t; cvta.to.shared.u64 t, %1; cvt.u32.u64 %0, t; }"
        : "=r"(a) : "l"(p));
    return a;
}
__device__ __forceinline__ void cpa16(uint32_t dst, const void* src) {
    asm volatile("cp.async.cg.shared.global [%0], [%1], 16;" :: "r"(dst), "l"(src));
}
#define CPA_COMMIT() asm volatile("cp.async.commit_group;" ::: "memory")
#define CPA_WAIT(n)  asm volatile("cp.async.wait_group %0;" :: "n"(n) : "memory")

#define LDSM4(r, addr)                                                          \
    asm volatile("ldmatrix.sync.aligned.m8n8.x4.shared.b16 {%0,%1,%2,%3}, [%4];"\
                 : "=r"((r)[0]), "=r"((r)[1]), "=r"((r)[2]), "=r"((r)[3])       \
                 : "r"(addr))
#define LDSM4T(r, addr)                                                         \
    asm volatile("ldmatrix.sync.aligned.m8n8.x4.trans.shared.b16 {%0,%1,%2,%3}, [%4];"\
                 : "=r"((r)[0]), "=r"((r)[1]), "=r"((r)[2]), "=r"((r)[3])       \
                 : "r"(addr))

// HMMA: D(16x8,f32) += A(16x16,f16,row) * B(16x8,f16,col)
__device__ __forceinline__ void mma16816(float* d, const uint32_t* a, const uint32_t* b) {
    asm volatile(
        "mma.sync.aligned.m16n8k16.row.col.f32.f16.f16.f32 "
        "{%0,%1,%2,%3}, {%4,%5,%6,%7}, {%8,%9}, {%0,%1,%2,%3};"
        : "+f"(d[0]), "+f"(d[1]), "+f"(d[2]), "+f"(d[3])
        : "r"(a[0]), "r"(a[1]), "r"(a[2]), "r"(a[3]), "r"(b[0]), "r"(b[1]));
}

__device__ __forceinline__ void split2h(float v, __half& h, __half& l) {
    h = __float2half(v);
    l = __float2half(v - __half2float(h));
}
__device__ __forceinline__ uint32_t packh2(__half a, __half b) {
    __half2 p = __halves2half2(a, b);
    return *(uint32_t*)&p;
}

// ======================= conversion kernels ===================================
// also zeroes the kv/ksum accumulators (merged zero_acc)
__global__ __launch_bounds__(256) void convert_x_kernel(const float* __restrict__ x)
{
    size_t i = (size_t)blockIdx.x * 256 + threadIdx.x;   // float4 index
    float4 v = ((const float4*)x)[i];
    __half h[4], l[4];
    split2h(v.x, h[0], l[0]); split2h(v.y, h[1], l[1]);
    split2h(v.z, h[2], l[2]); split2h(v.w, h[3], l[3]);
    *(uint2*)&g_xh[4 * i] = *(uint2*)h;
    *(uint2*)&g_xl[4 * i] = *(uint2*)l;
    if (i < BH_SZ * HD_SZ * HD_SZ) g_kv[i] = 0.f;
    if (i < BH_SZ * HD_SZ)         g_ksum[i] = 0.f;
}

// transpose 4 weights to fp16: Wt[w][n][k] = W_w[k][n]
__global__ void convert_w_kernel(const float* __restrict__ Wq, const float* __restrict__ Wk,
                                 const float* __restrict__ Wv, const float* __restrict__ Wo)
{
    __shared__ float tile[32][33];
    const int w = blockIdx.z;
    const float* W = (w == 0) ? Wq : (w == 1) ? Wk : (w == 2) ? Wv : Wo;
    int tx = threadIdx.x, ty = threadIdx.y;
    int k = blockIdx.y * 32 + ty;
    int n = blockIdx.x * 32 + tx;
    tile[ty][tx] = W[k * D_SZ + n];
    __syncthreads();
    int nn = blockIdx.x * 32 + ty;
    int kk = blockIdx.y * 32 + tx;
    float v = tile[tx][ty];
    size_t idx = (size_t)w * D_SZ * D_SZ + (size_t)nn * D_SZ + kk;
    g_wt[idx] = __float2half(v);
}

// ======================= tensor-core GEMM (mma.sync fp16, A-split) ============
// CTA tile 128x128, BK=32, 256 threads (8 warps, 4x2), warp tile 32x64.
// 2-stage cp.async pipeline; D = Ah*B + Al*B (A split fp16, B single fp16).
// MODE 0: fused QKV; q -> fp32 (featmap), k -> fp16 hi/lo (featmap), v -> fp16 hi/lo
// MODE 2: Wo (+bias, +resid) -> fp32
#define BKC     32
#define RSTRIDE 80           // bytes per smem row (32 fp16 + 16 pad)
#define A_BYTES (128 * RSTRIDE)
#define B_BYTES (128 * RSTRIDE)
#define AH_OFF  0
#define AL_OFF  (A_BYTES)
#define BH_OFF  (2 * A_BYTES)
#define STAGE_BYTES (2 * A_BYTES + B_BYTES)       // 30720
#define NSTAGE  2
#define NCHUNK  (D_SZ / BKC)                      // 16

template <int MODE>
__global__ __launch_bounds__(256, 2)
void gemm_tc(const __half* __restrict__ Ah, const __half* __restrict__ Al,
             const __half* __restrict__ Bh,
             const float* __restrict__ b0p, const float* __restrict__ b1p,
             const float* __restrict__ b2p, const float* __restrict__ resid,
             float* __restrict__ C0)
{
    extern __shared__ __align__(16) char dsm[];
    const uint32_t sb = smem_u32(dsm);

    const int t    = threadIdx.x;
    const int lane = t & 31;
    const int wid  = t >> 5;
    const int wm   = wid >> 1;          // 0..3  (32-row group)
    const int wn   = wid & 1;           // 0..1  (64-col group)
    const int m0   = blockIdx.y * 128;
    const int n0   = blockIdx.x * 128;

    float acc[2][8][4];
#pragma unroll
    for (int i = 0; i < 2; i++)
#pragma unroll
        for (int j = 0; j < 8; j++)
#pragma unroll
            for (int r = 0; r < 4; r++) acc[i][j][r] = 0.f;

    const uint32_t aoff = (uint32_t)(wm * 32 + (lane & 15)) * RSTRIDE
                        + ((lane >> 4) & 1) * 16;
    const uint32_t boff = (uint32_t)(wn * 64 + (lane & 7) + ((lane >> 4) & 1) * 8) * RSTRIDE
                        + ((lane >> 3) & 1) * 16;

    auto load_chunk = [&](int kc, int stage) {
        const uint32_t base = sb + stage * STAGE_BYTES;
        const size_t gkoff = (size_t)kc * BKC;
#pragma unroll
        for (int e = 0; e < 2; e++) {            // A: 128 rows x 4 parts = 512
            int id   = t + e * 256;
            int row  = id >> 2;
            int part = id & 3;
            uint32_t doff = row * RSTRIDE + part * 16;
            size_t   goff = (size_t)(m0 + row) * D_SZ + gkoff + part * 8;
            cpa16(base + AH_OFF + doff, Ah + goff);
            cpa16(base + AL_OFF + doff, Al + goff);
        }
#pragma unroll
        for (int e = 0; e < 2; e++) {            // B: 128 rows x 4 parts = 512
            int id   = t + e * 256;
            int row  = id >> 2;
            int part = id & 3;
            uint32_t doff = row * RSTRIDE + part * 16;
            size_t   goff = (size_t)(n0 + row) * D_SZ + gkoff + part * 8;
            cpa16(base + BH_OFF + doff, Bh + goff);
        }
        CPA_COMMIT();
    };

    auto compute_chunk = [&](int stage) {
        const uint32_t base = sb + stage * STAGE_BYTES;
        const uint32_t aH = base + AH_OFF + aoff;
        const uint32_t aL = base + AL_OFF + aoff;
        const uint32_t bH = base + BH_OFF + boff;
#pragma unroll
        for (int kk = 0; kk < 2; kk++) {
            const int cb = kk * 32;
            uint32_t fah[2][4], fal[2][4];
            LDSM4(fah[0], aH + cb);
            LDSM4(fah[1], aH + 16 * RSTRIDE + cb);
            LDSM4(fal[0], aL + cb);
            LDSM4(fal[1], aL + 16 * RSTRIDE + cb);
#pragma unroll
            for (int nh = 0; nh < 2; nh++) {
                const uint32_t bo2 = nh * 32 * RSTRIDE + cb;
                uint32_t fbh[2][4];
                LDSM4(fbh[0], bH + bo2);
                LDSM4(fbh[1], bH + bo2 + 16 * RSTRIDE);
#pragma unroll
                for (int mi = 0; mi < 2; mi++)
#pragma unroll
                    for (int nj = 0; nj < 4; nj++)
                        mma16816(acc[mi][nh * 4 + nj], fah[mi], &fbh[nj >> 1][(nj & 1) * 2]);
#pragma unroll
                for (int mi = 0; mi < 2; mi++)
#pragma unroll
                    for (int nj = 0; nj < 4; nj++)
                        mma16816(acc[mi][nh * 4 + nj], fal[mi], &fbh[nj >> 1][(nj & 1) * 2]);
            }
        }
    };

    load_chunk(0, 0);
    for (int c = 0; c < NCHUNK; c++) {
        if (c + 1 < NCHUNK) {
            load_chunk(c + 1, (c + 1) & 1);
            CPA_WAIT(1);
        } else {
            CPA_WAIT(0);
        }
        __syncthreads();
        compute_chunk(c & 1);
        __syncthreads();
    }

    // ---- epilogue ----
    const int wsel = (MODE == 0) ? (n0 >> 9) : 0;
    const float* bias = (MODE == 0) ? ((wsel == 0) ? b0p : (wsel == 1) ? b1p : b2p) : b0p;
    const int ncol0 = (MODE == 0) ? (n0 & 511) : n0;

    const int g  = lane >> 2;
    const int tg = lane & 3;
#pragma unroll
    for (int mi = 0; mi < 2; mi++) {
#pragma unroll
        for (int half = 0; half < 2; half++) {
            int row = m0 + wm * 32 + mi * 16 + g + half * 8;
            const float* Rrow = (MODE == 2) ? (resid + (size_t)row * D_SZ) : nullptr;
#pragma unroll
            for (int nj = 0; nj < 8; nj++) {
                int col = ncol0 + wn * 64 + nj * 8 + tg * 2;
                float v0 = acc[mi][nj][half * 2 + 0] + bias[col];
                float v1 = acc[mi][nj][half * 2 + 1] + bias[col + 1];
                if (MODE == 0) {
                    if (wsel < 2) {   // feature map for q and k
                        v0 = (v0 > 0.f) ? (v0 + 1.f) : __expf(v0);
                        v1 = (v1 > 0.f) ? (v1 + 1.f) : __expf(v1);
                    }
                    size_t idx = (size_t)row * D_SZ + col;
                    if (wsel == 0) {
                        *(float2*)&C0[idx] = make_float2(v0, v1);
                    } else {
                        __half h0, l0, h1, l1;
                        split2h(v0, h0, l0);
                        split2h(v1, h1, l1);
                        uint32_t hw = packh2(h0, h1), lw = packh2(l0, l1);
                        if (wsel == 1) {
                            *(uint32_t*)&g_kh[idx] = hw;
                            *(uint32_t*)&g_kl[idx] = lw;
                        } else {
                            *(uint32_t*)&g_vh[idx] = hw;
                            *(uint32_t*)&g_vl[idx] = lw;
                        }
                    }
                } else {
                    v0 += Rrow[col];
                    v1 += Rrow[col + 1];
                    *(float2*)&C0[(size_t)row * D_SZ + col] = make_float2(v0, v1);
                }
            }
        }
    }
}

// ---------------- kv = K^T V per (b,h) via HMMA, plus k_sum --------------------
// grid: (32 chunks of 256 rows, 32 bh). 256 threads = 8 warps.
// warp w: d0 = (w>>1)*16, m0 = (w&1)*32. 3 split terms: KhVh + KhVl + KlVh.
#define KVSTRIDE 144                       // bytes per smem row (64 fp16 + 8 pad)
__global__ __launch_bounds__(256)
void kv_kernel()
{
    __shared__ __half skh[64 * 72];
    __shared__ __half skl[64 * 72];
    __shared__ __half svh[64 * 72];
    __shared__ __half svl[64 * 72];

    const int bh    = blockIdx.y;
    const int chunk = blockIdx.x;          // 256-row chunk
    const int b = bh >> 3, h = bh & 7;
    const size_t tok0 = (size_t)b * S_SZ + chunk * 256;

    const int t    = threadIdx.x;
    const int lane = t & 31;
    const int wid  = t >> 5;
    const int d0   = (wid >> 1) * 16;
    const int m0   = (wid & 1) * 32;

    const uint32_t pkh = smem_u32(skh), pkl = smem_u32(skl);
    const uint32_t pvh = smem_u32(svh), pvl = smem_u32(svl);

    // ldmatrix.trans address offsets
    // A = K^T: row = (lane&7) + ((lane>>4)&1)*8 ; colbyte = d0*2 + ((lane>>3)&1)*16
    const uint32_t aoff = ((lane & 7) + ((lane >> 4) & 1) * 8) * KVSTRIDE
                        + d0 * 2 + ((lane >> 3) & 1) * 16;
    // B = V: row = (lane&7) + ((lane>>3)&1)*8 ; colbyte = m0*2 + ((lane>>4)&1)*16
    const uint32_t boff = ((lane & 7) + ((lane >> 3) & 1) * 8) * KVSTRIDE
                        + m0 * 2 + ((lane >> 4) & 1) * 16;

    float acc[4][4];
#pragma unroll
    for (int j = 0; j < 4; j++)
#pragma unroll
        for (int r = 0; r < 4; r++) acc[j][r] = 0.f;
    float ksl = 0.f;
    const int kcol  = t & 63;              // ksum column
    const int krow0 = (t >> 6) * 16;       // ksum row quarter

    for (int it = 0; it < 4; it++) {       // 4 tiles of 64 rows
        // load tiles: per buffer 64 rows x 8 parts(16B) = 512 tasks
#pragma unroll
        for (int e = 0; e < 2; e++) {
            int id   = t + e * 256;
            int row  = id >> 3;
            int part = id & 7;
            uint32_t doff = row * KVSTRIDE + part * 16;
            size_t   goff = (tok0 + it * 64 + row) * D_SZ + h * HD_SZ + part * 8;
            cpa16(pkh + doff, g_kh + goff);
            cpa16(pkl + doff, g_kl + goff);
            cpa16(pvh + doff, g_vh + goff);
            cpa16(pvl + doff, g_vl + goff);
        }
        CPA_COMMIT();
        CPA_WAIT(0);
        __syncthreads();

        // k_sum partial (fp32): each thread sums 16 rows of its column
#pragma unroll
        for (int r = 0; r < 16; r++) {
            int rr = krow0 + r;
            ksl += __half2float(skh[rr * 72 + kcol]) + __half2float(skl[rr * 72 + kcol]);
        }

        // HMMA: 4 k-steps of 16 rows
#pragma unroll
        for (int ks = 0; ks < 4; ks++) {
            const uint32_t so = ks * 16 * KVSTRIDE;
            uint32_t akh[4], akl[4], bvh0[4], bvh1[4], bvl0[4], bvl1[4];
            LDSM4T(akh, pkh + aoff + so);
            LDSM4T(akl, pkl + aoff + so);
            LDSM4T(bvh0, pvh + boff + so);
            LDSM4T(bvh1, pvh + boff + so + 32);
            LDSM4T(bvl0, pvl + boff + so);
            LDSM4T(bvl1, pvl + boff + so + 32);
            // n-blocks: j=0 {bvh0[0],[1]}, j=1 {bvh0[2],[3]}, j=2 {bvh1[0],[1]}, j=3 {bvh1[2],[3]}
#pragma unroll
            for (int j = 0; j < 4; j++) {
                const uint32_t* bh2 = (j < 2) ? &bvh0[(j & 1) * 2] : &bvh1[(j & 1) * 2];
                const uint32_t* bl2 = (j < 2) ? &bvl0[(j & 1) * 2] : &bvl1[(j & 1) * 2];
                mma16816(acc[j], akh, bh2);
                mma16816(acc[j], akh, bl2);
                mma16816(acc[j], akl, bh2);
            }
        }
        __syncthreads();
    }

    // ---- accumulate to global ----
    float* kvdst = g_kv + bh * (HD_SZ * HD_SZ);
    const int g  = lane >> 2;
    const int tg = lane & 3;
#pragma unroll
    for (int j = 0; j < 4; j++) {
        int col = m0 + j * 8 + tg * 2;
        atomicAdd(&kvdst[(d0 + g) * HD_SZ + col],         acc[j][0]);
        atomicAdd(&kvdst[(d0 + g) * HD_SZ + col + 1],     acc[j][1]);
        atomicAdd(&kvdst[(d0 + g + 8) * HD_SZ + col],     acc[j][2]);
        atomicAdd(&kvdst[(d0 + g + 8) * HD_SZ + col + 1], acc[j][3]);
    }
    atomicAdd(&g_ksum[bh * HD_SZ + kcol], ksl);
}

// ---------------- out = (q @ kv) / max(q . ksum, 1e-6), emits fp16 hi/lo ------
__global__ __launch_bounds__(256)
void attn_kernel()
{
    const int bh   = blockIdx.y;
    const int tile = blockIdx.x;
    const int b = bh >> 3, h = bh & 7;

    __shared__ float qs[64][68];
    __shared__ float kvb[64][64];
    __shared__ float ksb[64];
    __shared__ float nrm[64];

    const int t = threadIdx.x;
    const float* qb = g_q + ((size_t)(b * S_SZ + tile * 64)) * D_SZ + h * HD_SZ;

#pragma unroll
    for (int e = t; e < 1024; e += 256) {
        int r  = e >> 4;
        int c4 = (e & 15) << 2;
        *(float4*)&qs[r][c4] = *(const float4*)&qb[(size_t)r * D_SZ + c4];
    }
#pragma unroll
    for (int e = t; e < 1024; e += 256) {
        int r  = e >> 4;
        int c4 = (e & 15) << 2;
        *(float4*)&kvb[r][c4] = *(const float4*)&g_kv[bh * 4096 + r * 64 + c4];
    }
    if (t < 64) ksb[t] = g_ksum[bh * HD_SZ + t];
    __syncthreads();

    if (t < 64) {
        float s = 0.f;
#pragma unroll
        for (int d = 0; d < 64; d++) s = fmaf(qs[t][d], ksb[d], s);
        nrm[t] = fmaxf(s, 1e-6f);
    }
    __syncthreads();

    const int rg = (t >> 4) << 2;
    const int mg = (t & 15) << 2;
    float acc[4][4];
#pragma unroll
    for (int i = 0; i < 4; i++)
#pragma unroll
        for (int j = 0; j < 4; j++) acc[i][j] = 0.f;

#pragma unroll
    for (int kk = 0; kk < 64; kk++) {
        float a[4], bb[4];
#pragma unroll
        for (int i = 0; i < 4; i++) a[i] = qs[rg + i][kk];
        *(float4*)&bb[0] = *(float4*)&kvb[kk][mg];
#pragma unroll
        for (int i = 0; i < 4; i++)
#pragma unroll
            for (int j = 0; j < 4; j++)
                acc[i][j] = fmaf(a[i], bb[j], acc[i][j]);
    }

    size_t obase = ((size_t)(b * S_SZ + tile * 64)) * D_SZ + h * HD_SZ;
#pragma unroll
    for (int i = 0; i < 4; i++) {
        float inv = 1.0f / nrm[rg + i];
        __half hh[4], ll[4];
#pragma unroll
        for (int j = 0; j < 4; j++) {
            float v = acc[i][j] * inv;
            split2h(v, hh[j], ll[j]);
        }
        size_t idx = obase + (size_t)(rg + i) * D_SZ + mg;
        *(uint2*)&g_ah[idx] = *(uint2*)hh;
        *(uint2*)&g_al[idx] = *(uint2*)ll;
    }
}

// ---------------- LayerNorm over g_y -> out (float4) --------------------------
__global__ __launch_bounds__(256)
void ln_kernel(const float* __restrict__ gamma, const float* __restrict__ beta,
               float* __restrict__ out)
{
    const int row  = blockIdx.x * 8 + (threadIdx.x >> 5);
    const int lane = threadIdx.x & 31;
    const float4* y4 = (const float4*)(g_y + (size_t)row * D_SZ);

    float4 vals[4];
    float s = 0.f, s2 = 0.f;
#pragma unroll
    for (int i = 0; i < 4; i++) {
        float4 v = y4[lane + i * 32];
        vals[i] = v;
        s += v.x + v.y + v.z + v.w;
        s2 = fmaf(v.x, v.x, s2); s2 = fmaf(v.y, v.y, s2);
        s2 = fmaf(v.z, v.z, s2); s2 = fmaf(v.w, v.w, s2);
    }
#pragma unroll
    for (int o = 16; o > 0; o >>= 1) {
        s  += __shfl_xor_sync(0xFFFFFFFFu, s, o);
        s2 += __shfl_xor_sync(0xFFFFFFFFu, s2, o);
    }
    const float mean = s * (1.0f / 512.0f);
    const float var  = s2 * (1.0f / 512.0f) - mean * mean;
    const float inv  = rsqrtf(var + 1e-5f);

    const float4* g4 = (const float4*)gamma;
    const float4* b4 = (const float4*)beta;
    float4* o4 = (float4*)(out + (size_t)row * D_SZ);
#pragma unroll
    for (int i = 0; i < 4; i++) {
        int c = lane + i * 32;
        float4 g = g4[c], bb = b4[c], v = vals[i];
        float4 r;
        r.x = (v.x - mean) * inv * g.x + bb.x;
        r.y = (v.y - mean) * inv * g.y + bb.y;
        r.z = (v.z - mean) * inv * g.z + bb.z;
        r.w = (v.w - mean) * inv * g.w + bb.w;
        o4[c] = r;
    }
}

// ---------------- launch ------------------------------------------------------
extern "C" void kernel_launch(void* const* d_in, const int* in_sizes, int n_in,
                              void* d_out, int out_size)
{
    const float* x     = (const float*)d_in[0];
    const float* Wq    = (const float*)d_in[1];
    const float* bq    = (const float*)d_in[2];
    const float* Wk    = (const float*)d_in[3];
    const float* bk    = (const float*)d_in[4];
    const float* Wv    = (const float*)d_in[5];
    const float* bv    = (const float*)d_in[6];
    const float* Wo    = (const float*)d_in[7];
    const float* bo    = (const float*)d_in[8];
    const float* gamma = (const float*)d_in[9];
    const float* beta  = (const float*)d_in[10];
    float* out = (float*)d_out;

    __half *pxh, *pxl, *pwt, *pah, *pal;
    float *pq, *py;
    cudaGetSymbolAddress((void**)&pxh, g_xh);
    cudaGetSymbolAddress((void**)&pxl, g_xl);
    cudaGetSymbolAddress((void**)&pwt, g_wt);
    cudaGetSymbolAddress((void**)&pah, g_ah);
    cudaGetSymbolAddress((void**)&pal, g_al);
    cudaGetSymbolAddress((void**)&pq,  g_q);
    cudaGetSymbolAddress((void**)&py,  g_y);

    const int SMEM_DYN = NSTAGE * STAGE_BYTES;   // 61440
    cudaFuncSetAttribute(gemm_tc<0>, cudaFuncAttributeMaxDynamicSharedMemorySize, SMEM_DYN);
    cudaFuncSetAttribute(gemm_tc<2>, cudaFuncAttributeMaxDynamicSharedMemorySize, SMEM_DYN);

    // split input into fp16 hi/lo (+ zero kv/ksum accumulators), weights to fp16
    convert_x_kernel<<<(N_TOK * D_SZ / 4) / 256, 256>>>(x);
    convert_w_kernel<<<dim3(16, 16, 4), dim3(32, 32)>>>(Wq, Wk, Wv, Wo);

    // fused QKV projection: N_total = 1536 over [Wq|Wk|Wv]
    dim3 gqkv(3 * D_SZ / 128, N_TOK / 128);   // (12, 256)
    gemm_tc<0><<<gqkv, 256, SMEM_DYN>>>(pxh, pxl, pwt,
                                        bq, bk, bv, nullptr, pq);

    // kv summary + k_sum (tensor cores)
    kv_kernel<<<dim3(S_SZ / 256, BH_SZ), 256>>>();

    // normalized attention output (emits fp16 hi/lo for the Wo GEMM)
    attn_kernel<<<dim3(S_SZ / 64, BH_SZ), 256>>>();

    // output projection + residual
    dim3 gwo(D_SZ / 128, N_TOK / 128);        // (4, 256)
    gemm_tc<2><<<gwo, 256, SMEM_DYN>>>(pah, pal, pwt + 3 * D_SZ * D_SZ,
                                       bo, nullptr, nullptr, x, py);

    // layernorm
    ln_kernel<<<N_TOK / 8, 256>>>(gamma, beta, out);
}